// round 14
// baseline (speedup 1.0000x reference)
#include <cuda_runtime.h>
#include <math.h>

#define N_ROWS 65536
#define NBLK   64
#define NTHR   256
#define NLB    1024       // local buckets per owner block
#define CAP    1536       // slots per box (mean 1024, sd ~32 -> 16 sigma)

typedef unsigned long long ull;

// ---------------- scratch (zero-init at load; k2 resets for next call) ------
__device__ ull      g_boxk[NBLK * CAP];     // (keybits<<32)|row_idx
__device__ float2   g_boxe[NBLK * CAP];     // (e2, e3) payload
__device__ unsigned g_boxcnt[NBLK];
__device__ double   g_csum2[NBLK], g_csum3[NBLK], g_part[NBLK];
__device__ unsigned g_bar[2];
__device__ unsigned g_done;

__device__ __forceinline__ unsigned bucket_of(float k) {
    k = fminf(fmaxf(k, 0.0f), 0.999999f);
    unsigned b = (unsigned)(k * 65536.0f);
    return b > 65535u ? 65535u : b;
}

__device__ __forceinline__ void gbar(int i) {
    __syncthreads();
    if (threadIdx.x == 0) {
        __threadfence();
        atomicAdd(&g_bar[i], 1u);
        while (((volatile unsigned*)g_bar)[i] < NBLK) { }
        __threadfence();
    }
    __syncthreads();
}

// ===========================================================================
// K1: per-row cos-sim -> exp -> route (key, idx, e2, e3) to owner box.
// 4096 blocks x 256 threads, 2 rows/warp. DRAM-bandwidth bound; the routing
// (2 global atomics + 2 16B scattered stores per warp) hides under the stream.
// ===========================================================================
__global__ void __launch_bounds__(256)
k1_main(const float4* __restrict__ x,
        const float4* __restrict__ o2,
        const float4* __restrict__ o3,
        const float*  __restrict__ rank) {
    __shared__ float4 so2[128], so3[128];
    __shared__ float  red[8];
    __shared__ float  s_n2, s_n3;
    int t = threadIdx.x;
    if (t < 128)      so2[t]       = o2[t];
    else              so3[t - 128] = o3[t - 128];
    __syncthreads();

    float a;
    if (t < 128) { float4 v = so2[t];       a = v.x*v.x + v.y*v.y + v.z*v.z + v.w*v.w; }
    else         { float4 v = so3[t - 128]; a = v.x*v.x + v.y*v.y + v.z*v.z + v.w*v.w; }
#pragma unroll
    for (int o = 16; o > 0; o >>= 1) a += __shfl_xor_sync(0xFFFFFFFFu, a, o);
    int warp = t >> 5, lane = t & 31;
    if (lane == 0) red[warp] = a;
    __syncthreads();
    if (t == 0) {
        s_n2 = sqrtf(red[0] + red[1] + red[2] + red[3]);
        s_n3 = sqrtf(red[4] + red[5] + red[6] + red[7]);
    }
    __syncthreads();
    float n2 = s_n2, n3 = s_n3;

    int row0 = blockIdx.x * 16 + warp * 2;
    const float4* xa = x + (size_t)row0 * 128;
    const float4* xb = xa + 128;

    float d2a = 0.f, d3a = 0.f, nna = 0.f;
    float d2b = 0.f, d3b = 0.f, nnb = 0.f;
#pragma unroll
    for (int k = 0; k < 4; k++) {
        float4 va = xa[lane + 32 * k];
        float4 vb = xb[lane + 32 * k];
        float4 p  = so2[lane + 32 * k];
        float4 q  = so3[lane + 32 * k];
        d2a += va.x*p.x + va.y*p.y + va.z*p.z + va.w*p.w;
        d3a += va.x*q.x + va.y*q.y + va.z*q.z + va.w*q.w;
        nna += va.x*va.x + va.y*va.y + va.z*va.z + va.w*va.w;
        d2b += vb.x*p.x + vb.y*p.y + vb.z*p.z + vb.w*p.w;
        d3b += vb.x*q.x + vb.y*q.y + vb.z*q.z + vb.w*q.w;
        nnb += vb.x*vb.x + vb.y*vb.y + vb.z*vb.z + vb.w*vb.w;
    }
#pragma unroll
    for (int o = 16; o > 0; o >>= 1) {
        d2a += __shfl_xor_sync(0xFFFFFFFFu, d2a, o);
        d3a += __shfl_xor_sync(0xFFFFFFFFu, d3a, o);
        nna += __shfl_xor_sync(0xFFFFFFFFu, nna, o);
        d2b += __shfl_xor_sync(0xFFFFFFFFu, d2b, o);
        d3b += __shfl_xor_sync(0xFFFFFFFFu, d3b, o);
        nnb += __shfl_xor_sync(0xFFFFFFFFu, nnb, o);
    }
    if (lane == 0) {
        float nxa = sqrtf(nna), nxb = sqrtf(nnb);
        float e2a = expf(d2a / fmaxf(nxa * n2, 1e-8f));
        float e3a = expf(d3a / fmaxf(nxa * n3, 1e-8f));
        float e2b = expf(d2b / fmaxf(nxb * n2, 1e-8f));
        float e3b = expf(d3b / fmaxf(nxb * n3, 1e-8f));

        float ka = rank[row0], kb = rank[row0 + 1];
        unsigned ga = bucket_of(ka), gb = bucket_of(kb);
        unsigned boxa = ga >> 10, boxb = gb >> 10;
        unsigned pa = atomicAdd(&g_boxcnt[boxa], 1u);
        unsigned pb = atomicAdd(&g_boxcnt[boxb], 1u);
        if (pa < CAP) {
            g_boxk[boxa * CAP + pa] =
                ((ull)__float_as_uint(ka) << 32) | (unsigned)row0;
            g_boxe[boxa * CAP + pa] = make_float2(e2a, e3a);
        }
        if (pb < CAP) {
            g_boxk[boxb * CAP + pb] =
                ((ull)__float_as_uint(kb) << 32) | (unsigned)(row0 + 1);
            g_boxe[boxb * CAP + pb] = make_float2(e2b, e3b);
        }
    }
}

// ===========================================================================
// K2 (64 x 256): load my pre-routed box -> smem bucket sort (with payload)
// -> sums -> ONE gbar -> 64-scan -> prefix+logs -> finish.
// ===========================================================================
__global__ void __launch_bounds__(256)
k2_fused(float* __restrict__ out) {
    __shared__ ull      s_list[CAP];                 // unsorted keys
    __shared__ ull      s_skey[CAP];                 // sorted keys
    __shared__ float2   s_sval[CAP];                 // sorted (e2,e3)
    __shared__ unsigned s_lhist[NLB], s_lofs[NLB];
    __shared__ unsigned s_wtu[8];
    __shared__ double   s_wt2[8], s_wt3[8];
    __shared__ double   s_c2[NBLK], s_c3[NBLK];
    __shared__ bool     amLast;

    int t = threadIdx.x, blk = blockIdx.x;
    int warp = t >> 5, lane = t & 31;

    unsigned n_loc = __ldcg(&g_boxcnt[blk]);
    if (n_loc > CAP) n_loc = CAP;

    for (int j = t; j < NLB; j += NTHR) s_lhist[j] = 0u;
    __syncthreads();

    // ---- load keys + local histogram --------------------------------------
    for (unsigned i = t; i < n_loc; i += NTHR) {
        ull e = __ldcg(&g_boxk[blk * CAP + i]);
        s_list[i] = e;
        unsigned g = bucket_of(__uint_as_float((unsigned)(e >> 32))) & 1023u;
        atomicAdd(&s_lhist[g], 1u);
    }
    __syncthreads();

    // ---- block exclusive scan of 1024 bins (4 per thread) ------------------
    unsigned b0 = t * 4;
    unsigned h[4], ofs[4];
#pragma unroll
    for (int j = 0; j < 4; j++) h[j] = s_lhist[b0 + j];
    unsigned hs = h[0] + h[1] + h[2] + h[3];
    unsigned v = hs;
#pragma unroll
    for (int o = 1; o < 32; o <<= 1) {
        unsigned u = __shfl_up_sync(0xFFFFFFFFu, v, o);
        if (lane >= o) v += u;
    }
    if (lane == 31) s_wtu[warp] = v;
    __syncthreads();
    if (t < 8) {
        unsigned x = s_wtu[t];
#pragma unroll
        for (int o = 1; o < 8; o <<= 1) {
            unsigned u = __shfl_up_sync(0xFFu, x, o);
            if (t >= o) x += u;
        }
        s_wtu[t] = x;
    }
    __syncthreads();
    unsigned exth = v + (warp ? s_wtu[warp - 1] : 0u) - hs;
    ofs[0] = exth;
    ofs[1] = ofs[0] + h[0];
    ofs[2] = ofs[1] + h[1];
    ofs[3] = ofs[2] + h[2];
#pragma unroll
    for (int j = 0; j < 4; j++) { s_lofs[b0 + j] = ofs[j]; s_lhist[b0 + j] = 0u; }
    __syncthreads();

    // ---- scatter into bucket slots (keys + payload from L2) ----------------
    for (unsigned i = t; i < n_loc; i += NTHR) {
        ull e = s_list[i];
        unsigned g = bucket_of(__uint_as_float((unsigned)(e >> 32))) & 1023u;
        unsigned slot = s_lofs[g] + atomicAdd(&s_lhist[g], 1u);
        s_skey[slot] = e;
        s_sval[slot] = __ldcg(&g_boxe[blk * CAP + i]);
    }
    __syncthreads();

    // ---- in-bucket selection sort, payload travels (deterministic u64 order)
#pragma unroll
    for (int j = 0; j < 4; j++) {
        unsigned hh = h[j];
        if (hh >= 2u) {
            unsigned base = ofs[j];
            for (unsigned p = 0; p + 1 < hh; p++) {
                unsigned m = p;
                for (unsigned q = p + 1; q < hh; q++)
                    if (s_skey[base + q] < s_skey[base + m]) m = q;
                if (m != p) {
                    ull tk = s_skey[base + p];
                    s_skey[base + p] = s_skey[base + m];
                    s_skey[base + m] = tk;
                    float2 tv = s_sval[base + p];
                    s_sval[base + p] = s_sval[base + m];
                    s_sval[base + m] = tv;
                }
            }
        }
    }
    __syncthreads();

    // ---- local sums --------------------------------------------------------
    double sum2 = 0.0, sum3 = 0.0;
    for (unsigned i = t; i < n_loc; i += NTHR) {
        float2 ev = s_sval[i];
        sum2 += ev.x; sum3 += ev.y;
    }
    {
        double a2 = sum2, a3 = sum3;
#pragma unroll
        for (int o = 16; o > 0; o >>= 1) {
            a2 += __shfl_xor_sync(0xFFFFFFFFu, a2, o);
            a3 += __shfl_xor_sync(0xFFFFFFFFu, a3, o);
        }
        if (lane == 0) { s_wt2[warp] = a2; s_wt3[warp] = a3; }
        __syncthreads();
        if (t == 0) {
            double c2 = 0.0, c3 = 0.0;
            for (int j = 0; j < 8; j++) { c2 += s_wt2[j]; c3 += s_wt3[j]; }
            g_csum2[blk] = c2; g_csum3[blk] = c3;
        }
    }
    gbar(0);                                          // the one grid barrier

    // ---- 64-scan of block sums (redundant); prefix + logs ------------------
    if (t < NBLK) { s_c2[t] = __ldcg(&g_csum2[t]); s_c3[t] = __ldcg(&g_csum3[t]); }
    __syncthreads();
#pragma unroll
    for (int o = 1; o < NBLK; o <<= 1) {
        double u2 = (t >= o && t < NBLK) ? s_c2[t - o] : 0.0;
        double u3 = (t >= o && t < NBLK) ? s_c3[t - o] : 0.0;
        __syncthreads();
        if (t < NBLK) { s_c2[t] += u2; s_c3[t] += u3; }
        __syncthreads();
    }
    double tot2 = s_c2[NBLK - 1], tot3 = s_c3[NBLK - 1];
    double carry2 = (blk > 0) ? s_c2[blk - 1] : 0.0;
    double carry3 = (blk > 0) ? s_c3[blk - 1] : 0.0;

    double ls = 0.0;
    int R = (int)((n_loc + NTHR - 1) / NTHR);
    for (int r = 0; r < R; r++) {
        int i = r * NTHR + t;
        bool valid = i < (int)n_loc;
        double v2 = 0.0, v3 = 0.0;
        if (valid) { float2 ev = s_sval[i]; v2 = ev.x; v3 = ev.y; }
#pragma unroll
        for (int o = 1; o < 32; o <<= 1) {
            double u2 = __shfl_up_sync(0xFFFFFFFFu, v2, o);
            double u3 = __shfl_up_sync(0xFFFFFFFFu, v3, o);
            if (lane >= o) { v2 += u2; v3 += u3; }
        }
        if (lane == 31) { s_wt2[warp] = v2; s_wt3[warp] = v3; }
        __syncthreads();
        if (t < 8) {
            double x2 = s_wt2[t], x3 = s_wt3[t];
#pragma unroll
            for (int o = 1; o < 8; o <<= 1) {
                double u2 = __shfl_up_sync(0xFFu, x2, o);
                double u3 = __shfl_up_sync(0xFFu, x3, o);
                if (t >= o) { x2 += u2; x3 += u3; }
            }
            s_wt2[t] = x2; s_wt3[t] = x3;
        }
        __syncthreads();
        if (valid) {
            double incl2 = v2 + (warp ? s_wt2[warp - 1] : 0.0);
            double incl3 = v3 + (warp ? s_wt3[warp - 1] : 0.0);
            ls += (double)logf((float)(carry2 + incl2)) +
                  (double)logf((float)(carry3 + incl3));
        }
        carry2 += s_wt2[7];
        carry3 += s_wt3[7];
        __syncthreads();
    }

#pragma unroll
    for (int o = 16; o > 0; o >>= 1) ls += __shfl_xor_sync(0xFFFFFFFFu, ls, o);
    if (lane == 0) s_wt2[warp] = ls;
    __syncthreads();
    if (t == 0) {
        double s = 0.0;
        for (int j = 0; j < 8; j++) s += s_wt2[j];
        g_part[blk] = s;
    }

    // ---- Final: last block reduces partials, writes out, resets state ------
    if (t == 0) {
        __threadfence();
        amLast = (atomicAdd(&g_done, 1u) == NBLK - 1);
    }
    __syncthreads();
    if (amLast) {
        double p = (t < NBLK) ? __ldcg(&g_part[t]) : 0.0;
#pragma unroll
        for (int o = 16; o > 0; o >>= 1) p += __shfl_xor_sync(0xFFFFFFFFu, p, o);
        __syncthreads();
        if (lane == 0) s_wt2[warp] = p;
        __syncthreads();
        if (t == 0) {
            double s = 0.0;
            for (int j = 0; j < 8; j++) s += s_wt2[j];
            out[0] = (float)((double)N_ROWS * (log(tot2) + log(tot3)) - s);
            g_done  = 0u;
            g_bar[0] = 0u;
        }
        if (t < NBLK) g_boxcnt[t] = 0u;   // every block read its count already
    }
}

extern "C" void kernel_launch(void* const* d_in, const int* in_sizes, int n_in,
                              void* d_out, int out_size) {
    const float* o1   = (const float*)d_in[0];  // [65536, 512]
    const float* o2   = (const float*)d_in[1];  // [1, 512]
    const float* o3   = (const float*)d_in[2];  // [1, 512]
    const float* rank = (const float*)d_in[3];  // [65536]
    float* out = (float*)d_out;

    k1_main<<<N_ROWS / 16, 256>>>((const float4*)o1, (const float4*)o2,
                                  (const float4*)o3, rank);
    k2_fused<<<NBLK, NTHR>>>(out);
}

// round 16
// speedup vs baseline: 1.1943x; 1.1943x over previous
#include <cuda_runtime.h>
#include <math.h>

#define N_ROWS 65536
#define NBLK   64
#define NTHR   1024
#define NLB    1024       // local buckets per owner block
#define CAP    1536       // slots per box (mean 1024, sd ~32 -> 16 sigma)

typedef unsigned long long ull;

// ---------------- scratch (zero-init at load; k2 resets for next call) ------
__device__ float    g_e2[N_ROWS], g_e3[N_ROWS];
__device__ ull      g_boxk[NBLK * CAP];
__device__ unsigned g_boxcnt[NBLK];
__device__ double   g_csum2[NBLK], g_csum3[NBLK], g_part[NBLK];
__device__ unsigned g_bar[2];
__device__ unsigned g_done;

__device__ __forceinline__ unsigned bucket_of(float k) {
    k = fminf(fmaxf(k, 0.0f), 0.999999f);
    unsigned b = (unsigned)(k * 65536.0f);
    return b > 65535u ? 65535u : b;
}

__device__ __forceinline__ void gbar(int i) {
    __syncthreads();
    if (threadIdx.x == 0) {
        __threadfence();
        atomicAdd(&g_bar[i], 1u);
        while (((volatile unsigned*)g_bar)[i] < NBLK) { }
        __threadfence();
    }
    __syncthreads();
}

// ===========================================================================
// K1: per-row cos-sim -> exp. 2 rows/warp, 4096 blocks x 256. BW-bound.
// (No routing, no histogram — R14 showed the atomic hotspot costs ~20us.)
// ===========================================================================
__global__ void __launch_bounds__(256)
k1_main(const float4* __restrict__ x,
        const float4* __restrict__ o2,
        const float4* __restrict__ o3) {
    __shared__ float4 so2[128], so3[128];
    __shared__ float  red[8];
    __shared__ float  s_n2, s_n3;
    int t = threadIdx.x;
    if (t < 128)      so2[t]       = o2[t];
    else              so3[t - 128] = o3[t - 128];
    __syncthreads();

    float a;
    if (t < 128) { float4 v = so2[t];       a = v.x*v.x + v.y*v.y + v.z*v.z + v.w*v.w; }
    else         { float4 v = so3[t - 128]; a = v.x*v.x + v.y*v.y + v.z*v.z + v.w*v.w; }
#pragma unroll
    for (int o = 16; o > 0; o >>= 1) a += __shfl_xor_sync(0xFFFFFFFFu, a, o);
    int warp = t >> 5, lane = t & 31;
    if (lane == 0) red[warp] = a;
    __syncthreads();
    if (t == 0) {
        s_n2 = sqrtf(red[0] + red[1] + red[2] + red[3]);
        s_n3 = sqrtf(red[4] + red[5] + red[6] + red[7]);
    }
    __syncthreads();
    float n2 = s_n2, n3 = s_n3;

    int row0 = blockIdx.x * 16 + warp * 2;
    const float4* xa = x + (size_t)row0 * 128;
    const float4* xb = xa + 128;

    float d2a = 0.f, d3a = 0.f, nna = 0.f;
    float d2b = 0.f, d3b = 0.f, nnb = 0.f;
#pragma unroll
    for (int k = 0; k < 4; k++) {
        float4 va = xa[lane + 32 * k];
        float4 vb = xb[lane + 32 * k];
        float4 p  = so2[lane + 32 * k];
        float4 q  = so3[lane + 32 * k];
        d2a += va.x*p.x + va.y*p.y + va.z*p.z + va.w*p.w;
        d3a += va.x*q.x + va.y*q.y + va.z*q.z + va.w*q.w;
        nna += va.x*va.x + va.y*va.y + va.z*va.z + va.w*va.w;
        d2b += vb.x*p.x + vb.y*p.y + vb.z*p.z + vb.w*p.w;
        d3b += vb.x*q.x + vb.y*q.y + vb.z*q.z + vb.w*q.w;
        nnb += vb.x*vb.x + vb.y*vb.y + vb.z*vb.z + vb.w*vb.w;
    }
#pragma unroll
    for (int o = 16; o > 0; o >>= 1) {
        d2a += __shfl_xor_sync(0xFFFFFFFFu, d2a, o);
        d3a += __shfl_xor_sync(0xFFFFFFFFu, d3a, o);
        nna += __shfl_xor_sync(0xFFFFFFFFu, nna, o);
        d2b += __shfl_xor_sync(0xFFFFFFFFu, d2b, o);
        d3b += __shfl_xor_sync(0xFFFFFFFFu, d3b, o);
        nnb += __shfl_xor_sync(0xFFFFFFFFu, nnb, o);
    }
    if (lane == 0) {
        float nxa = sqrtf(nna), nxb = sqrtf(nnb);
        g_e2[row0]     = expf(d2a / fmaxf(nxa * n2, 1e-8f));
        g_e3[row0]     = expf(d3a / fmaxf(nxa * n3, 1e-8f));
        g_e2[row0 + 1] = expf(d2b / fmaxf(nxb * n2, 1e-8f));
        g_e3[row0 + 1] = expf(d3b / fmaxf(nxb * n3, 1e-8f));
    }
}

// ===========================================================================
// K2 (64 blocks x 1024 threads): route (1 key/thread, aggregated atomics) ->
// gbar -> local smem sort -> gather+sums -> gbar -> prefix+logs -> finish.
// ===========================================================================
__global__ void __launch_bounds__(1024)
k2_fused(const float* __restrict__ rank, float* __restrict__ out) {
    __shared__ union {
        ull list[CAP];
        struct { float e2[CAP]; float e3[CAP]; } e;
    } uA;
    __shared__ ull      s_skey[CAP];
    __shared__ unsigned s_lhist[NLB], s_lofs[NLB];
    __shared__ unsigned s_bh[NBLK], s_bofs[NBLK], s_bcnt[NBLK];
    __shared__ unsigned s_wtu[32];
    __shared__ double   s_wt2[32], s_wt3[32];
    __shared__ double   s_c2[NBLK], s_c3[NBLK];
    __shared__ bool     amLast;

    int t = threadIdx.x, blk = blockIdx.x;
    int warp = t >> 5, lane = t & 31;

    // ---- Phase A: route my 1 key to its owner box (aggregated atomics) -----
    if (t < NBLK) { s_bh[t] = 0u; s_bcnt[t] = 0u; }
    __syncthreads();
    int gi = blk * 1024 + t;
    float key = rank[gi];
    unsigned gbkt = bucket_of(key);
    unsigned box = gbkt >> 10;
    atomicAdd(&s_bh[box], 1u);
    __syncthreads();
    if (t < NBLK && s_bh[t] != 0u)
        s_bofs[t] = atomicAdd(&g_boxcnt[t], s_bh[t]);
    __syncthreads();
    {
        unsigned pos = s_bofs[box] + atomicAdd(&s_bcnt[box], 1u);
        if (pos < CAP)
            g_boxk[box * CAP + pos] =
                ((ull)__float_as_uint(key) << 32) | (unsigned)gi;
    }
    gbar(0);

    // ---- Phase B: load my box; smem bucket sort ----------------------------
    unsigned n_loc = __ldcg(&g_boxcnt[blk]);
    if (n_loc > CAP) n_loc = CAP;

    s_lhist[t] = 0u;
    __syncthreads();
    for (unsigned i = t; i < n_loc; i += NTHR) {
        ull e = __ldcg(&g_boxk[blk * CAP + i]);
        uA.list[i] = e;
        unsigned g = bucket_of(__uint_as_float((unsigned)(e >> 32))) & 1023u;
        atomicAdd(&s_lhist[g], 1u);
    }
    __syncthreads();

    // block exclusive scan of 1024 bins (1/thread, 32 warps + leader scan)
    unsigned h = s_lhist[t];
    unsigned v = h;
#pragma unroll
    for (int o = 1; o < 32; o <<= 1) {
        unsigned u = __shfl_up_sync(0xFFFFFFFFu, v, o);
        if (lane >= o) v += u;
    }
    if (lane == 31) s_wtu[warp] = v;
    __syncthreads();
    if (t < 32) {
        unsigned x = s_wtu[t];
#pragma unroll
        for (int o = 1; o < 32; o <<= 1) {
            unsigned u = __shfl_up_sync(0xFFFFFFFFu, x, o);
            if (t >= o) x += u;
        }
        s_wtu[t] = x;
    }
    __syncthreads();
    unsigned ofs = v + (warp ? s_wtu[warp - 1] : 0u) - h;   // exclusive
    s_lofs[t]  = ofs;
    s_lhist[t] = 0u;
    __syncthreads();

    // scatter into bucket slots
    for (unsigned i = t; i < n_loc; i += NTHR) {
        ull e = uA.list[i];
        unsigned g = bucket_of(__uint_as_float((unsigned)(e >> 32))) & 1023u;
        unsigned slot = s_lofs[g] + atomicAdd(&s_lhist[g], 1u);
        s_skey[slot] = e;
    }
    __syncthreads();

    // in-bucket selection sort (bucket t; u64 total order -> deterministic)
    if (h >= 2u) {
        for (unsigned p = 0; p + 1 < h; p++) {
            unsigned m = p;
            for (unsigned q = p + 1; q < h; q++)
                if (s_skey[ofs + q] < s_skey[ofs + m]) m = q;
            if (m != p) {
                ull tk = s_skey[ofs + p];
                s_skey[ofs + p] = s_skey[ofs + m];
                s_skey[ofs + m] = tk;
            }
        }
    }
    __syncthreads();

    // ---- Phase C: gather e2/e3 (L2), local sums ----------------------------
    double sum2 = 0.0, sum3 = 0.0;
    for (unsigned i = t; i < n_loc; i += NTHR) {
        unsigned idx = (unsigned)(s_skey[i] & 0xFFFFFFFFu);
        float e2v = __ldcg(&g_e2[idx]), e3v = __ldcg(&g_e3[idx]);
        uA.e.e2[i] = e2v; uA.e.e3[i] = e3v;
        sum2 += e2v; sum3 += e3v;
    }
    {
        double a2 = sum2, a3 = sum3;
#pragma unroll
        for (int o = 16; o > 0; o >>= 1) {
            a2 += __shfl_xor_sync(0xFFFFFFFFu, a2, o);
            a3 += __shfl_xor_sync(0xFFFFFFFFu, a3, o);
        }
        if (lane == 0) { s_wt2[warp] = a2; s_wt3[warp] = a3; }
        __syncthreads();
        if (t == 0) {
            double c2 = 0.0, c3 = 0.0;
            for (int j = 0; j < 32; j++) { c2 += s_wt2[j]; c3 += s_wt3[j]; }
            g_csum2[blk] = c2; g_csum3[blk] = c3;
        }
    }
    gbar(1);

    // ---- Phase D: 64-scan of block sums (redundant); prefix + logs ---------
    if (t < NBLK) { s_c2[t] = __ldcg(&g_csum2[t]); s_c3[t] = __ldcg(&g_csum3[t]); }
    __syncthreads();
#pragma unroll
    for (int o = 1; o < NBLK; o <<= 1) {
        double u2 = (t >= o && t < NBLK) ? s_c2[t - o] : 0.0;
        double u3 = (t >= o && t < NBLK) ? s_c3[t - o] : 0.0;
        __syncthreads();
        if (t < NBLK) { s_c2[t] += u2; s_c3[t] += u3; }
        __syncthreads();
    }
    double tot2 = s_c2[NBLK - 1], tot3 = s_c3[NBLK - 1];
    double carry2 = (blk > 0) ? s_c2[blk - 1] : 0.0;
    double carry3 = (blk > 0) ? s_c3[blk - 1] : 0.0;

    double ls = 0.0;
    int R = (int)((n_loc + NTHR - 1) / NTHR);
    for (int r = 0; r < R; r++) {
        unsigned i = (unsigned)(r * NTHR + t);
        bool valid = i < n_loc;
        double v2 = valid ? (double)uA.e.e2[i] : 0.0;
        double v3 = valid ? (double)uA.e.e3[i] : 0.0;
#pragma unroll
        for (int o = 1; o < 32; o <<= 1) {
            double u2 = __shfl_up_sync(0xFFFFFFFFu, v2, o);
            double u3 = __shfl_up_sync(0xFFFFFFFFu, v3, o);
            if (lane >= o) { v2 += u2; v3 += u3; }
        }
        if (lane == 31) { s_wt2[warp] = v2; s_wt3[warp] = v3; }
        __syncthreads();
        if (t < 32) {
            double x2 = s_wt2[t], x3 = s_wt3[t];
#pragma unroll
            for (int o = 1; o < 32; o <<= 1) {
                double u2 = __shfl_up_sync(0xFFFFFFFFu, x2, o);
                double u3 = __shfl_up_sync(0xFFFFFFFFu, x3, o);
                if (t >= o) { x2 += u2; x3 += u3; }
            }
            s_wt2[t] = x2; s_wt3[t] = x3;
        }
        __syncthreads();
        if (valid) {
            double incl2 = v2 + (warp ? s_wt2[warp - 1] : 0.0);
            double incl3 = v3 + (warp ? s_wt3[warp - 1] : 0.0);
            ls += (double)logf((float)(carry2 + incl2)) +
                  (double)logf((float)(carry3 + incl3));
        }
        carry2 += s_wt2[31];
        carry3 += s_wt3[31];
        __syncthreads();
    }

#pragma unroll
    for (int o = 16; o > 0; o >>= 1) ls += __shfl_xor_sync(0xFFFFFFFFu, ls, o);
    if (lane == 0) s_wt2[warp] = ls;
    __syncthreads();
    if (t == 0) {
        double s = 0.0;
        for (int j = 0; j < 32; j++) s += s_wt2[j];
        g_part[blk] = s;
    }

    // ---- Final: last block reduces partials, writes out, resets state ------
    if (t == 0) {
        __threadfence();
        amLast = (atomicAdd(&g_done, 1u) == NBLK - 1);
    }
    __syncthreads();
    if (amLast) {
        double p = (t < NBLK) ? __ldcg(&g_part[t]) : 0.0;
#pragma unroll
        for (int o = 16; o > 0; o >>= 1) p += __shfl_xor_sync(0xFFFFFFFFu, p, o);
        __syncthreads();
        if (lane == 0) s_wt2[warp] = p;
        __syncthreads();
        if (t == 0) {
            double s = 0.0;
            for (int j = 0; j < 2; j++) s += s_wt2[j];   // only warps 0-1 hold data
            out[0] = (float)((double)N_ROWS * (log(tot2) + log(tot3)) - s);
            g_done   = 0u;
            g_bar[0] = 0u;
            g_bar[1] = 0u;
        }
        if (t < NBLK) g_boxcnt[t] = 0u;
    }
}

extern "C" void kernel_launch(void* const* d_in, const int* in_sizes, int n_in,
                              void* d_out, int out_size) {
    const float* o1   = (const float*)d_in[0];  // [65536, 512]
    const float* o2   = (const float*)d_in[1];  // [1, 512]
    const float* o3   = (const float*)d_in[2];  // [1, 512]
    const float* rank = (const float*)d_in[3];  // [65536]
    float* out = (float*)d_out;

    k1_main<<<N_ROWS / 16, 256>>>((const float4*)o1, (const float4*)o2,
                                  (const float4*)o3);
    k2_fused<<<NBLK, NTHR>>>(rank, out);
}

// round 17
// speedup vs baseline: 1.3382x; 1.1205x over previous
#include <cuda_runtime.h>
#include <math.h>

#define N_ROWS 65536
#define NBLK   128
#define NTHR   1024
#define RPB    512        // rows per block
#define NLB    512        // local bins per box (128 boxes * 512 = 65536 buckets)
#define CAP    768        // box capacity (Poisson mean 512, sd 22.6 -> 11 sigma)

typedef unsigned long long ull;

// ---------------- scratch (zero-init at load; kernel resets at exit) --------
__device__ ulonglong2 g_box[NBLK * CAP];    // {(key<<32)|idx, (e3<<32)|e2}
__device__ unsigned   g_boxcnt[NBLK];
__device__ double     g_csum2[NBLK], g_csum3[NBLK], g_part[NBLK];
__device__ unsigned   g_bar[2];
__device__ unsigned   g_done;

__device__ __forceinline__ unsigned bucket_of(float k) {
    k = fminf(fmaxf(k, 0.0f), 0.999999f);
    unsigned b = (unsigned)(k * 65536.0f);
    return b > 65535u ? 65535u : b;
}

__device__ __forceinline__ void gbar(int i) {
    __syncthreads();
    if (threadIdx.x == 0) {
        __threadfence();
        atomicAdd(&g_bar[i], 1u);
        while (((volatile unsigned*)g_bar)[i] < NBLK) { }
        __threadfence();
    }
    __syncthreads();
}

// ===========================================================================
// ONE kernel: cos-sim+exp (512 rows/block) -> aggregated routing -> gbar ->
// local smem box sort -> sums -> gbar -> scan -> prefix+logs -> finish.
// 128 blocks x 1024 threads, single wave.
// ===========================================================================
__global__ void __launch_bounds__(1024)
k_all(const float4* __restrict__ x,
      const float4* __restrict__ o2,
      const float4* __restrict__ o3,
      const float*  __restrict__ rank,
      float* __restrict__ out) {
    __shared__ float4   so2[128], so3[128];
    __shared__ ulonglong2 s_uns[CAP];                  // unsorted box
    __shared__ union {
        ulonglong2 stage[RPB];                         // staging (dead after route)
        ulonglong2 sorted[CAP];                        // sorted box
    } uS;
    __shared__ unsigned s_lhist[NLB], s_lofs[NLB];
    __shared__ unsigned s_bh[NBLK], s_bofs[NBLK], s_bcnt[NBLK];
    __shared__ unsigned s_wtu[16];
    __shared__ float    red[8];
    __shared__ float    s_n2, s_n3;
    __shared__ double   s_wt2[32], s_wt3[32];
    __shared__ double   s_c2[NBLK], s_c3[NBLK];
    __shared__ bool     amLast;

    int t = threadIdx.x, blk = blockIdx.x;
    int warp = t >> 5, lane = t & 31;

    if (t < 128)       so2[t]       = o2[t];
    else if (t < 256)  so3[t - 128] = o3[t - 128];
    if (t < NBLK) { s_bh[t] = 0u; s_bcnt[t] = 0u; }
    __syncthreads();

    // ---- norms (redundant per block) ---------------------------------------
    {
        float a = 0.f;
        if (t < 128)       { float4 v = so2[t];       a = v.x*v.x + v.y*v.y + v.z*v.z + v.w*v.w; }
        else if (t < 256)  { float4 v = so3[t - 128]; a = v.x*v.x + v.y*v.y + v.z*v.z + v.w*v.w; }
#pragma unroll
        for (int o = 16; o > 0; o >>= 1) a += __shfl_xor_sync(0xFFFFFFFFu, a, o);
        if (warp < 8 && lane == 0) red[warp] = a;
        __syncthreads();
        if (t == 0) {
            s_n2 = sqrtf(red[0] + red[1] + red[2] + red[3]);
            s_n3 = sqrtf(red[4] + red[5] + red[6] + red[7]);
        }
        __syncthreads();
    }
    float n2 = s_n2, n3 = s_n3;

    // ---- Phase 1: cos-sim + exp for my 512 rows (16 rows/warp, 2 at a time)
    for (int rr = 0; rr < 16; rr += 2) {
        int row0 = blk * RPB + warp * 16 + rr;
        const float4* xa = x + (size_t)row0 * 128;
        const float4* xb = xa + 128;
        float d2a = 0.f, d3a = 0.f, nna = 0.f;
        float d2b = 0.f, d3b = 0.f, nnb = 0.f;
#pragma unroll
        for (int k = 0; k < 4; k++) {
            float4 va = xa[lane + 32 * k];
            float4 vb = xb[lane + 32 * k];
            float4 p  = so2[lane + 32 * k];
            float4 q  = so3[lane + 32 * k];
            d2a += va.x*p.x + va.y*p.y + va.z*p.z + va.w*p.w;
            d3a += va.x*q.x + va.y*q.y + va.z*q.z + va.w*q.w;
            nna += va.x*va.x + va.y*va.y + va.z*va.z + va.w*va.w;
            d2b += vb.x*p.x + vb.y*p.y + vb.z*p.z + vb.w*p.w;
            d3b += vb.x*q.x + vb.y*q.y + vb.z*q.z + vb.w*q.w;
            nnb += vb.x*vb.x + vb.y*vb.y + vb.z*vb.z + vb.w*vb.w;
        }
#pragma unroll
        for (int o = 16; o > 0; o >>= 1) {
            d2a += __shfl_xor_sync(0xFFFFFFFFu, d2a, o);
            d3a += __shfl_xor_sync(0xFFFFFFFFu, d3a, o);
            nna += __shfl_xor_sync(0xFFFFFFFFu, nna, o);
            d2b += __shfl_xor_sync(0xFFFFFFFFu, d2b, o);
            d3b += __shfl_xor_sync(0xFFFFFFFFu, d3b, o);
            nnb += __shfl_xor_sync(0xFFFFFFFFu, nnb, o);
        }
        if (lane == 0) {
            float nxa = sqrtf(nna), nxb = sqrtf(nnb);
            float e2a = expf(d2a / fmaxf(nxa * n2, 1e-8f));
            float e3a = expf(d3a / fmaxf(nxa * n3, 1e-8f));
            float e2b = expf(d2b / fmaxf(nxb * n2, 1e-8f));
            float e3b = expf(d3b / fmaxf(nxb * n3, 1e-8f));
            float ka = rank[row0], kb = rank[row0 + 1];
            int sa = warp * 16 + rr;
            uS.stage[sa] = make_ulonglong2(
                ((ull)__float_as_uint(ka) << 32) | (unsigned)row0,
                ((ull)__float_as_uint(e3a) << 32) | __float_as_uint(e2a));
            uS.stage[sa + 1] = make_ulonglong2(
                ((ull)__float_as_uint(kb) << 32) | (unsigned)(row0 + 1),
                ((ull)__float_as_uint(e3b) << 32) | __float_as_uint(e2b));
        }
    }
    __syncthreads();

    // ---- Phase 2: aggregated routing to owner boxes ------------------------
    ulonglong2 my_e;
    unsigned   my_box = 0u;
    if (t < RPB) {
        my_e = uS.stage[t];
        my_box = bucket_of(__uint_as_float((unsigned)(my_e.x >> 32))) >> 9;
        atomicAdd(&s_bh[my_box], 1u);
    }
    __syncthreads();
    if (t < NBLK && s_bh[t] != 0u)
        s_bofs[t] = atomicAdd(&g_boxcnt[t], s_bh[t]);
    __syncthreads();
    if (t < RPB) {
        unsigned pos = s_bofs[my_box] + atomicAdd(&s_bcnt[my_box], 1u);
        if (pos < CAP) g_box[my_box * CAP + pos] = my_e;
    }
    gbar(0);

    // ---- Phase 3: load my box; smem bucket sort ----------------------------
    unsigned n_loc = __ldcg(&g_boxcnt[blk]);
    if (n_loc > CAP) n_loc = CAP;

    if (t < NLB) s_lhist[t] = 0u;
    __syncthreads();
    if ((unsigned)t < n_loc) {
        ulonglong2 e = __ldcg(&g_box[blk * CAP + t]);
        s_uns[t] = e;
        unsigned bin = bucket_of(__uint_as_float((unsigned)(e.x >> 32))) & 511u;
        atomicAdd(&s_lhist[bin], 1u);
    }
    __syncthreads();

    // exclusive scan of 512 bins (threads 0-511 = 16 warps)
    unsigned h = 0u, ofs = 0u;
    {
        unsigned v = 0u;
        if (t < NLB) { h = s_lhist[t]; v = h; }
#pragma unroll
        for (int o = 1; o < 32; o <<= 1) {
            unsigned u = __shfl_up_sync(0xFFFFFFFFu, v, o);
            if (lane >= o) v += u;
        }
        if (t < NLB && lane == 31) s_wtu[warp] = v;
        __syncthreads();
        if (t < 16) {
            unsigned x = s_wtu[t];
#pragma unroll
            for (int o = 1; o < 16; o <<= 1) {
                unsigned u = __shfl_up_sync(0xFFFFu, x, o);
                if (t >= o) x += u;
            }
            s_wtu[t] = x;
        }
        __syncthreads();
        if (t < NLB) {
            ofs = v + (warp ? s_wtu[warp - 1] : 0u) - h;
            s_lofs[t]  = ofs;
            s_lhist[t] = 0u;
        }
        __syncthreads();
    }

    // scatter into bin slots
    if ((unsigned)t < n_loc) {
        ulonglong2 e = s_uns[t];
        unsigned bin = bucket_of(__uint_as_float((unsigned)(e.x >> 32))) & 511u;
        unsigned slot = s_lofs[bin] + atomicAdd(&s_lhist[bin], 1u);
        uS.sorted[slot] = e;
    }
    __syncthreads();

    // in-bin selection sort on unique u64 keys (deterministic)
    if (t < NLB && h >= 2u) {
        for (unsigned p = 0; p + 1 < h; p++) {
            unsigned m = p;
            for (unsigned q = p + 1; q < h; q++)
                if (uS.sorted[ofs + q].x < uS.sorted[ofs + m].x) m = q;
            if (m != p) {
                ulonglong2 tmp = uS.sorted[ofs + p];
                uS.sorted[ofs + p] = uS.sorted[ofs + m];
                uS.sorted[ofs + m] = tmp;
            }
        }
    }
    __syncthreads();

    // ---- Phase 4: local sums -----------------------------------------------
    double v2 = 0.0, v3 = 0.0;
    if ((unsigned)t < n_loc) {
        ulonglong2 e = uS.sorted[t];
        v2 = (double)__uint_as_float((unsigned)(e.y & 0xFFFFFFFFu));
        v3 = (double)__uint_as_float((unsigned)(e.y >> 32));
    }
    {
        double a2 = v2, a3 = v3;
#pragma unroll
        for (int o = 16; o > 0; o >>= 1) {
            a2 += __shfl_xor_sync(0xFFFFFFFFu, a2, o);
            a3 += __shfl_xor_sync(0xFFFFFFFFu, a3, o);
        }
        if (lane == 0) { s_wt2[warp] = a2; s_wt3[warp] = a3; }
        __syncthreads();
        if (t == 0) {
            double c2 = 0.0, c3 = 0.0;
            for (int j = 0; j < 32; j++) { c2 += s_wt2[j]; c3 += s_wt3[j]; }
            g_csum2[blk] = c2; g_csum3[blk] = c3;
        }
    }
    gbar(1);

    // ---- Phase 5: redundant 128-scan of block sums -------------------------
    if (t < NBLK) { s_c2[t] = __ldcg(&g_csum2[t]); s_c3[t] = __ldcg(&g_csum3[t]); }
    __syncthreads();
#pragma unroll
    for (int o = 1; o < NBLK; o <<= 1) {
        double u2 = (t >= o && t < NBLK) ? s_c2[t - o] : 0.0;
        double u3 = (t >= o && t < NBLK) ? s_c3[t - o] : 0.0;
        __syncthreads();
        if (t < NBLK) { s_c2[t] += u2; s_c3[t] += u3; }
        __syncthreads();
    }
    double tot2 = s_c2[NBLK - 1], tot3 = s_c3[NBLK - 1];
    double carry2 = (blk > 0) ? s_c2[blk - 1] : 0.0;
    double carry3 = (blk > 0) ? s_c3[blk - 1] : 0.0;

    // ---- Phase 6: single-round prefix + logs (n_loc <= 768 < 1024) ---------
    {
        double p2 = v2, p3 = v3;
#pragma unroll
        for (int o = 1; o < 32; o <<= 1) {
            double u2 = __shfl_up_sync(0xFFFFFFFFu, p2, o);
            double u3 = __shfl_up_sync(0xFFFFFFFFu, p3, o);
            if (lane >= o) { p2 += u2; p3 += u3; }
        }
        if (lane == 31) { s_wt2[warp] = p2; s_wt3[warp] = p3; }
        __syncthreads();
        if (t < 32) {
            double x2 = s_wt2[t], x3 = s_wt3[t];
#pragma unroll
            for (int o = 1; o < 32; o <<= 1) {
                double u2 = __shfl_up_sync(0xFFFFFFFFu, x2, o);
                double u3 = __shfl_up_sync(0xFFFFFFFFu, x3, o);
                if (t >= o) { x2 += u2; x3 += u3; }
            }
            s_wt2[t] = x2; s_wt3[t] = x3;
        }
        __syncthreads();
        double ls = 0.0;
        if ((unsigned)t < n_loc) {
            double incl2 = p2 + (warp ? s_wt2[warp - 1] : 0.0);
            double incl3 = p3 + (warp ? s_wt3[warp - 1] : 0.0);
            ls = (double)logf((float)(carry2 + incl2)) +
                 (double)logf((float)(carry3 + incl3));
        }
        __syncthreads();
#pragma unroll
        for (int o = 16; o > 0; o >>= 1) ls += __shfl_xor_sync(0xFFFFFFFFu, ls, o);
        if (lane == 0) s_wt2[warp] = ls;
        __syncthreads();
        if (t == 0) {
            double s = 0.0;
            for (int j = 0; j < 32; j++) s += s_wt2[j];
            g_part[blk] = s;
        }
    }

    // ---- Final: last block reduces partials, writes out, resets state ------
    if (t == 0) {
        __threadfence();
        amLast = (atomicAdd(&g_done, 1u) == NBLK - 1);
    }
    __syncthreads();
    if (amLast) {
        double p = (t < NBLK) ? __ldcg(&g_part[t]) : 0.0;
#pragma unroll
        for (int o = 16; o > 0; o >>= 1) p += __shfl_xor_sync(0xFFFFFFFFu, p, o);
        __syncthreads();
        if (lane == 0) s_wt2[warp] = p;
        __syncthreads();
        if (t == 0) {
            double s = 0.0;
            for (int j = 0; j < 4; j++) s += s_wt2[j];   // 128 partials = warps 0-3
            out[0] = (float)((double)N_ROWS * (log(tot2) + log(tot3)) - s);
            g_done   = 0u;
            g_bar[0] = 0u;
            g_bar[1] = 0u;
        }
        if (t < NBLK) g_boxcnt[t] = 0u;
    }
}

extern "C" void kernel_launch(void* const* d_in, const int* in_sizes, int n_in,
                              void* d_out, int out_size) {
    const float* o1   = (const float*)d_in[0];  // [65536, 512]
    const float* o2   = (const float*)d_in[1];  // [1, 512]
    const float* o3   = (const float*)d_in[2];  // [1, 512]
    const float* rank = (const float*)d_in[3];  // [65536]
    float* out = (float*)d_out;

    k_all<<<NBLK, NTHR>>>((const float4*)o1, (const float4*)o2,
                          (const float4*)o3, rank, out);
}